// round 14
// baseline (speedup 1.0000x reference)
#include <cuda_runtime.h>
#include <cuda_fp16.h>
#include <cstdint>

// Problem dims
#define Bb   64
#define Tt   256
#define Cc   384
#define Hh   6
#define HSZ  64
#define MM   (Bb*Tt)     // 16384 tokens
#define NQKV (3*Cc)      // 1152
#define FF   (4*Cc)      // 1536

// ================= helpers =================
__device__ __forceinline__ uint32_t smem_u32(const void* p) {
    uint32_t a;
    asm("{ .reg .u64 t; cvta.to.shared.u64 t, %1; cvt.u32.u64 %0, t; }" : "=r"(a) : "l"(p));
    return a;
}
#define SMEM_SWIZZLE_128B(off) ((off) ^ (((off) >> 3) & 0x70))

#define CP_ASYNC16(dst, src) \
    asm volatile("cp.async.cg.shared.global [%0], [%1], 16;" :: "r"(dst), "l"(src))
#define CP_COMMIT() asm volatile("cp.async.commit_group;" ::: "memory")
#define CP_WAIT(n)  asm volatile("cp.async.wait_group %0;" :: "n"(n) : "memory")

#define LDSM_X4(r0, r1, r2, r3, addr) \
    asm volatile("ldmatrix.sync.aligned.m8n8.x4.shared.b16 {%0,%1,%2,%3}, [%4];" \
        : "=r"(r0), "=r"(r1), "=r"(r2), "=r"(r3) : "r"(addr))

#define LDSM_X4_T(r0, r1, r2, r3, addr) \
    asm volatile("ldmatrix.sync.aligned.m8n8.x4.trans.shared.b16 {%0,%1,%2,%3}, [%4];" \
        : "=r"(r0), "=r"(r1), "=r"(r2), "=r"(r3) : "r"(addr))

#define MMA16816F16(d, a, b) \
    asm volatile("mma.sync.aligned.m16n8k16.row.col.f32.f16.f16.f32 " \
        "{%0,%1,%2,%3}, {%4,%5,%6,%7}, {%8,%9}, {%0,%1,%2,%3};" \
        : "+f"((d)[0]), "+f"((d)[1]), "+f"((d)[2]), "+f"((d)[3]) \
        : "r"((a)[0]), "r"((a)[1]), "r"((a)[2]), "r"((a)[3]), "r"((b)[0]), "r"((b)[1]))

__device__ __forceinline__ uint32_t pack_h2(float a, float b) {
    __half2 h = __floats2half2_rn(a, b);
    return *reinterpret_cast<uint32_t*>(&h);
}

// ================= scratch (device globals) =================
__device__ __align__(16) __half g_h   [MM*Cc];
__device__ __align__(16) __half g_qkvh[MM*NQKV];   // fp16 q|k|v
__device__ __align__(16) __half g_o   [MM*Cc];
__device__ __align__(16) float  g_x1  [MM*Cc];
__device__ __align__(16) __half g_h2  [MM*Cc];
__device__ __align__(16) __half g_ff  [MM*FF];
// weights: single fp16, transposed to [N][K]
__device__ __align__(16) __half g_wqkvT[NQKV*Cc];
__device__ __align__(16) __half g_wpT  [Cc*Cc];
__device__ __align__(16) __half g_w1T  [FF*Cc];
__device__ __align__(16) __half g_w2T  [Cc*FF];

// ================= fused weight pack (one launch) =================
#define SEG0 (NQKV*Cc)
#define SEG1 (Cc*Cc)
#define SEG2 (FF*Cc)
#define SEG3 (Cc*FF)
#define PACK_TOTAL (SEG0+SEG1+SEG2+SEG3)

__global__ void pack_all_kernel(const float* __restrict__ Wq, const float* __restrict__ Wk,
                                const float* __restrict__ Wv, const float* __restrict__ Wp,
                                const float* __restrict__ W1, const float* __restrict__ W2) {
    int idx = blockIdx.x * 256 + threadIdx.x;
    if (idx < SEG0) {
        int n = idx / Cc, k = idx % Cc;
        int which = n / Cc, hd = n % Cc;
        int h = hd / HSZ, d = hd % HSZ;
        const float* W = (which == 0) ? Wq : (which == 1) ? Wk : Wv;
        g_wqkvT[idx] = __float2half(W[(h * Cc + k) * HSZ + d]);
        return;
    }
    idx -= SEG0;
    if (idx < SEG1) {
        int n = idx / Cc, k = idx % Cc;
        g_wpT[idx] = __float2half(Wp[(size_t)k * Cc + n]);
        return;
    }
    idx -= SEG1;
    if (idx < SEG2) {
        int n = idx / Cc, k = idx % Cc;
        g_w1T[idx] = __float2half(W1[(size_t)k * FF + n]);
        return;
    }
    idx -= SEG2;
    if (idx < SEG3) {
        int n = idx / FF, k = idx % FF;
        g_w2T[idx] = __float2half(W2[(size_t)k * Cc + n]);
        return;
    }
}

// ================= LayerNorm (warp per row) =================
__global__ __launch_bounds__(256)
void ln_kernel(const float* __restrict__ x,
               const float* __restrict__ gamma,
               const float* __restrict__ beta,
               __half* __restrict__ y) {
    int row  = blockIdx.x * 8 + (threadIdx.x >> 5);
    int lane = threadIdx.x & 31;
    const float* xr = x + (size_t)row * Cc;
    float v[12];
    float s = 0.f, sq = 0.f;
    #pragma unroll
    for (int i = 0; i < 12; i++) {
        v[i] = xr[lane + 32 * i];
        s += v[i];
        sq += v[i] * v[i];
    }
    #pragma unroll
    for (int o = 16; o > 0; o >>= 1) {
        s  += __shfl_xor_sync(0xffffffffu, s,  o);
        sq += __shfl_xor_sync(0xffffffffu, sq, o);
    }
    float mu  = s / (float)Cc;
    float inv = rsqrtf(sq / (float)Cc - mu * mu + 1e-3f);
    size_t base = (size_t)row * Cc;
    #pragma unroll
    for (int i = 0; i < 12; i++) {
        int c = lane + 32 * i;
        y[base + c] = __float2half((v[i] - mu) * inv * gamma[c] + beta[c]);
    }
}

// ================= mma.sync fp16 GEMM, templated tile-N =====================
// C[M,N] = A[M,K] * B^T, A=[M][K] fp16, B=[N][K] fp16.
// CTA tile 128 x TN, BK=64, 3-stage cp.async pipeline, one barrier per chunk.
// 256 threads / 8 warps, warp grid 2(m) x 4(n) -> warp tile 64 x (TN/4).
template<int ROWS>
__device__ __forceinline__ void load_tile_async(const __half* __restrict__ src,
                                                int row0, int k0, int Ktot,
                                                uint32_t dstbase, int tid) {
    #pragma unroll
    for (int j = 0; j < ROWS / 32; j++) {
        int idx = tid + j * 256;
        int r = idx >> 3, c16 = idx & 7;
        const __half* g = src + (size_t)(row0 + r) * Ktot + k0 + c16 * 8;
        uint32_t s = dstbase + SMEM_SWIZZLE_128B((uint32_t)(r * 128 + c16 * 16));
        CP_ASYNC16(s, g);
    }
}

template<int TN, int BIAS, int RES, int RELU, int F32OUT, int HOUT>
__global__ __launch_bounds__(256)
void mma_gemm_kernel(const __half* __restrict__ A,
                     const __half* __restrict__ Bw,
                     const float* __restrict__ bias, const float* __restrict__ res,
                     float* __restrict__ Cf, __half* __restrict__ Ch,
                     int M, int N, int K) {
    constexpr int WTN  = TN / 4;          // warp tile n (32 or 16)
    constexpr int NF   = WTN / 8;         // 8-col fragments per warp (4 or 2)
    constexpr int NF2  = WTN / 16;        // 16-col ldmatrix groups (2 or 1)
    constexpr uint32_t ABYTES = 16384;
    constexpr uint32_t BBYTES = TN * 128;
    constexpr uint32_t BUF    = ABYTES + BBYTES;

    extern __shared__ char dsm[];
    uint32_t raw  = smem_u32(dsm);
    uint32_t base = (raw + 1023) & ~1023u;

    int tid = threadIdx.x, wid = tid >> 5, lane = tid & 31;
    int warp_m = (wid >> 2) * 64;
    int warp_n = (wid & 3) * WTN;
    int m0 = blockIdx.y * 128, n0 = blockIdx.x * TN;
    int nch = K >> 6;

    float acc[4][NF][4];
    #pragma unroll
    for (int a = 0; a < 4; a++)
        #pragma unroll
        for (int b = 0; b < NF; b++)
            #pragma unroll
            for (int c = 0; c < 4; c++) acc[a][b][c] = 0.f;

    // prologue: chunks 0,1 -> bufs 0,1
    load_tile_async<128>(A,  m0, 0, K, base + 0,      tid);
    load_tile_async<TN >(Bw, n0, 0, K, base + ABYTES, tid);
    CP_COMMIT();
    if (nch > 1) {
        load_tile_async<128>(A,  m0, 64, K, base + BUF + 0,      tid);
        load_tile_async<TN >(Bw, n0, 64, K, base + BUF + ABYTES, tid);
        CP_COMMIT();
    }

    int q = lane >> 3, rin = lane & 7;
    int a_row_off = (q & 1) * 8 + rin;
    int a_col_off = (q >> 1) * 8;
    int b_row_off = (q >> 1) * 8 + rin;
    int b_col_off = (q & 1) * 8;

    for (int i = 0; i < nch; i++) {
        if (i + 1 < nch) { CP_WAIT(1); } else { CP_WAIT(0); }
        __syncthreads();

        uint32_t buf = base + (uint32_t)(i % 3) * BUF;
        uint32_t sA = buf + 0, sB = buf + ABYTES;

        #pragma unroll
        for (int ks = 0; ks < 4; ks++) {
            uint32_t af[4][4], bw[NF][2];
            #pragma unroll
            for (int mf = 0; mf < 4; mf++) {
                uint32_t off = (uint32_t)((warp_m + mf * 16 + a_row_off) * 128 +
                                          (ks * 16 + a_col_off) * 2);
                LDSM_X4(af[mf][0], af[mf][1], af[mf][2], af[mf][3],
                        sA + SMEM_SWIZZLE_128B(off));
            }
            #pragma unroll
            for (int nf2 = 0; nf2 < NF2; nf2++) {
                uint32_t off = (uint32_t)((warp_n + nf2 * 16 + b_row_off) * 128 +
                                          (ks * 16 + b_col_off) * 2);
                LDSM_X4(bw[nf2 * 2][0], bw[nf2 * 2][1], bw[nf2 * 2 + 1][0], bw[nf2 * 2 + 1][1],
                        sB + SMEM_SWIZZLE_128B(off));
            }
            #pragma unroll
            for (int mf = 0; mf < 4; mf++)
                #pragma unroll
                for (int nf = 0; nf < NF; nf++) MMA16816F16(acc[mf][nf], af[mf], bw[nf]);
        }

        if (i + 2 < nch) {
            uint32_t nb = base + (uint32_t)((i + 2) % 3) * BUF;
            int k0 = (i + 2) << 6;
            load_tile_async<128>(A,  m0, k0, K, nb + 0,      tid);
            load_tile_async<TN >(Bw, n0, k0, K, nb + ABYTES, tid);
            CP_COMMIT();
        }
    }

    int tr = lane >> 2, tc = (lane & 3) * 2;
    #pragma unroll
    for (int mf = 0; mf < 4; mf++) {
        #pragma unroll
        for (int nf = 0; nf < NF; nf++) {
            int col = n0 + warp_n + nf * 8 + tc;
            #pragma unroll
            for (int half = 0; half < 2; half++) {
                int row = m0 + warp_m + mf * 16 + tr + half * 8;
                float v0 = acc[mf][nf][half * 2 + 0];
                float v1 = acc[mf][nf][half * 2 + 1];
                if (BIAS) { v0 += bias[col]; v1 += bias[col + 1]; }
                size_t oidx = (size_t)row * N + col;
                if (RES)  { v0 += res[oidx]; v1 += res[oidx + 1]; }
                if (RELU) { v0 = fmaxf(v0, 0.f); v1 = fmaxf(v1, 0.f); }
                if (F32OUT) { Cf[oidx] = v0; Cf[oidx + 1] = v1; }
                if (HOUT) {
                    Ch[oidx]     = __float2half(v0);
                    Ch[oidx + 1] = __float2half(v1);
                }
            }
        }
    }
}

// ================= flash attention (mma.sync fp16) =================
__device__ __forceinline__ void fattn_load_kv(const __half* __restrict__ qkv,
                                              int b, int h, int kt,
                                              uint32_t kbase, uint32_t vbase, int tid) {
    #pragma unroll
    for (int j = 0; j < 4; j++) {
        int idx = tid + j * 128;
        int r = idx >> 3, c = idx & 7;
        const __half* ks = qkv + (size_t)(b * Tt + kt * 64 + r) * NQKV + Cc + h * HSZ + c * 8;
        CP_ASYNC16(kbase + SMEM_SWIZZLE_128B((uint32_t)(r * 128 + c * 16)), ks);
    }
    #pragma unroll
    for (int j = 0; j < 4; j++) {
        int idx = tid + j * 128;
        int r = idx >> 3, c = idx & 7;
        const __half* vs = qkv + (size_t)(b * Tt + kt * 64 + r) * NQKV + 2 * Cc + h * HSZ + c * 8;
        CP_ASYNC16(vbase + SMEM_SWIZZLE_128B((uint32_t)(r * 128 + c * 16)), vs);
    }
}

__global__ __launch_bounds__(128)
void fattn_kernel(const __half* __restrict__ qkv, __half* __restrict__ o) {
    __shared__ __align__(1024) __half smem[5 * 4096];
    int tid = threadIdx.x, wid = tid >> 5, lane = tid & 31;
    int b = blockIdx.z, h = blockIdx.y, qt = blockIdx.x;
    uint32_t sbase = smem_u32(smem);
    uint32_t qb = sbase;
    uint32_t kb0 = sbase + 8192,  kb1 = sbase + 16384;
    uint32_t vb0 = sbase + 24576, vb1 = sbase + 32768;

    #pragma unroll
    for (int j = 0; j < 4; j++) {
        int idx = tid + j * 128;
        int r = idx >> 3, c = idx & 7;
        const __half* src = qkv + (size_t)(b * Tt + qt * 64 + r) * NQKV + h * HSZ + c * 8;
        CP_ASYNC16(qb + SMEM_SWIZZLE_128B((uint32_t)(r * 128 + c * 16)), src);
    }
    fattn_load_kv(qkv, b, h, 0, kb0, vb0, tid);
    CP_COMMIT();
    CP_WAIT(0);
    __syncthreads();

    int q8 = lane >> 3, rin = lane & 7;
    int a_row = (q8 & 1) * 8 + rin, a_col = (q8 >> 1) * 8;
    int b_row = (q8 >> 1) * 8 + rin, b_col = (q8 & 1) * 8;
    int vm = lane >> 3;
    int v_row = (vm & 1) * 8 + (lane & 7);
    int v_col = (vm >> 1) * 8;
    int tg = lane & 3, gid = lane >> 2;

    uint32_t qf[4][4];
    #pragma unroll
    for (int kc = 0; kc < 4; kc++)
        LDSM_X4(qf[kc][0], qf[kc][1], qf[kc][2], qf[kc][3],
                qb + SMEM_SWIZZLE_128B((uint32_t)((wid * 16 + a_row) * 128 + (kc * 16 + a_col) * 2)));

    float oacc[8][4];
    #pragma unroll
    for (int d = 0; d < 8; d++)
        #pragma unroll
        for (int e = 0; e < 4; e++) oacc[d][e] = 0.f;
    float m0 = -1e30f, m1 = -1e30f, l0 = 0.f, l1 = 0.f;

    for (int kt = 0; kt <= qt; kt++) {
        uint32_t kb = (kt & 1) ? kb1 : kb0;
        uint32_t vb = (kt & 1) ? vb1 : vb0;
        if (kt < qt) {
            fattn_load_kv(qkv, b, h, kt + 1, (kt & 1) ? kb0 : kb1, (kt & 1) ? vb0 : vb1, tid);
            CP_COMMIT();
        }

        float sacc[8][4];
        #pragma unroll
        for (int n = 0; n < 8; n++)
            #pragma unroll
            for (int e = 0; e < 4; e++) sacc[n][e] = 0.f;
        #pragma unroll
        for (int kc = 0; kc < 4; kc++) {
            uint32_t bw[8][2];
            #pragma unroll
            for (int nf2 = 0; nf2 < 4; nf2++)
                LDSM_X4(bw[nf2 * 2][0], bw[nf2 * 2][1], bw[nf2 * 2 + 1][0], bw[nf2 * 2 + 1][1],
                        kb + SMEM_SWIZZLE_128B((uint32_t)((nf2 * 16 + b_row) * 128 + (kc * 16 + b_col) * 2)));
            #pragma unroll
            for (int nf = 0; nf < 8; nf++) MMA16816F16(sacc[nf], qf[kc], bw[nf]);
        }

        #pragma unroll
        for (int nf = 0; nf < 8; nf++)
            #pragma unroll
            for (int e = 0; e < 4; e++) sacc[nf][e] *= 0.125f;
        if (kt == qt) {
            int r0 = wid * 16 + gid, r1 = r0 + 8;
            #pragma unroll
            for (int nf = 0; nf < 8; nf++) {
                int c0 = nf * 8 + tg * 2;
                if (c0     > r0) sacc[nf][0] = -1e30f;
                if (c0 + 1 > r0) sacc[nf][1] = -1e30f;
                if (c0     > r1) sacc[nf][2] = -1e30f;
                if (c0 + 1 > r1) sacc[nf][3] = -1e30f;
            }
        }

        float rm0 = -1e30f, rm1 = -1e30f;
        #pragma unroll
        for (int nf = 0; nf < 8; nf++) {
            rm0 = fmaxf(rm0, fmaxf(sacc[nf][0], sacc[nf][1]));
            rm1 = fmaxf(rm1, fmaxf(sacc[nf][2], sacc[nf][3]));
        }
        rm0 = fmaxf(rm0, __shfl_xor_sync(0xffffffffu, rm0, 1));
        rm0 = fmaxf(rm0, __shfl_xor_sync(0xffffffffu, rm0, 2));
        rm1 = fmaxf(rm1, __shfl_xor_sync(0xffffffffu, rm1, 1));
        rm1 = fmaxf(rm1, __shfl_xor_sync(0xffffffffu, rm1, 2));
        float mn0 = fmaxf(m0, rm0), mn1 = fmaxf(m1, rm1);
        float cr0 = __expf(m0 - mn0), cr1 = __expf(m1 - mn1);
        l0 *= cr0; l1 *= cr1;
        #pragma unroll
        for (int d = 0; d < 8; d++) {
            oacc[d][0] *= cr0; oacc[d][1] *= cr0;
            oacc[d][2] *= cr1; oacc[d][3] *= cr1;
        }
        m0 = mn0; m1 = mn1;

        uint32_t pf[4][4];
        #pragma unroll
        for (int sf = 0; sf < 4; sf++) {
            float e00 = __expf(sacc[2 * sf][0] - m0);
            float e01 = __expf(sacc[2 * sf][1] - m0);
            float e02 = __expf(sacc[2 * sf][2] - m1);
            float e03 = __expf(sacc[2 * sf][3] - m1);
            float e10 = __expf(sacc[2 * sf + 1][0] - m0);
            float e11 = __expf(sacc[2 * sf + 1][1] - m0);
            float e12 = __expf(sacc[2 * sf + 1][2] - m1);
            float e13 = __expf(sacc[2 * sf + 1][3] - m1);
            l0 += e00 + e01 + e10 + e11;
            l1 += e02 + e03 + e12 + e13;
            pf[sf][0] = pack_h2(e00, e01);
            pf[sf][1] = pack_h2(e02, e03);
            pf[sf][2] = pack_h2(e10, e11);
            pf[sf][3] = pack_h2(e12, e13);
        }

        #pragma unroll
        for (int sf = 0; sf < 4; sf++) {
            uint32_t vf[8][2];
            #pragma unroll
            for (int dp = 0; dp < 4; dp++)
                LDSM_X4_T(vf[dp * 2][0], vf[dp * 2][1], vf[dp * 2 + 1][0], vf[dp * 2 + 1][1],
                          vb + SMEM_SWIZZLE_128B((uint32_t)((sf * 16 + v_row) * 128 + (dp * 16 + v_col) * 2)));
            #pragma unroll
            for (int df = 0; df < 8; df++) MMA16816F16(oacc[df], pf[sf], vf[df]);
        }

        if (kt < qt) { CP_WAIT(0); __syncthreads(); }
    }

    l0 += __shfl_xor_sync(0xffffffffu, l0, 1);
    l0 += __shfl_xor_sync(0xffffffffu, l0, 2);
    l1 += __shfl_xor_sync(0xffffffffu, l1, 1);
    l1 += __shfl_xor_sync(0xffffffffu, l1, 2);
    float i0 = 1.f / l0, i1 = 1.f / l1;
    size_t tok0 = (size_t)(b * Tt + qt * 64 + wid * 16 + gid);
    #pragma unroll
    for (int df = 0; df < 8; df++) {
        int col = h * HSZ + df * 8 + tg * 2;
        __half2 h0 = __floats2half2_rn(oacc[df][0] * i0, oacc[df][1] * i0);
        *reinterpret_cast<__half2*>(o + tok0 * Cc + col) = h0;
        __half2 h1 = __floats2half2_rn(oacc[df][2] * i1, oacc[df][3] * i1);
        *reinterpret_cast<__half2*>(o + (tok0 + 8) * Cc + col) = h1;
    }
}

// ================= host launch =================
template <typename T>
static T* sym_addr(const T* symbol) {
    void* p = nullptr;
    cudaGetSymbolAddress(&p, (const void*)symbol);
    return (T*)p;
}

#define DSMEM_TN(TN) (1024 + 3 * (16384 + (TN) * 128))

extern "C" void kernel_launch(void* const* d_in, const int* in_sizes, int n_in,
                              void* d_out, int out_size) {
    const float* x   = (const float*)d_in[0];
    const float* Wq  = (const float*)d_in[1];
    const float* Wk  = (const float*)d_in[2];
    const float* Wv  = (const float*)d_in[3];
    const float* Wp  = (const float*)d_in[4];
    const float* bp  = (const float*)d_in[5];
    const float* W1  = (const float*)d_in[6];
    const float* b1  = (const float*)d_in[7];
    const float* W2  = (const float*)d_in[8];
    const float* b2  = (const float*)d_in[9];
    const float* g1  = (const float*)d_in[10];
    const float* be1 = (const float*)d_in[11];
    const float* g2  = (const float*)d_in[12];
    const float* be2 = (const float*)d_in[13];
    float* out = (float*)d_out;

    __half* p_h    = sym_addr(g_h);
    __half* p_qkvh = sym_addr(g_qkvh);
    __half* p_o    = sym_addr(g_o);
    float*  p_x1   = sym_addr(g_x1);
    __half* p_h2   = sym_addr(g_h2);
    __half* p_ff   = sym_addr(g_ff);
    __half* p_wqkvT = sym_addr(g_wqkvT);
    __half* p_wpT   = sym_addr(g_wpT);
    __half* p_w1T   = sym_addr(g_w1T);
    __half* p_w2T   = sym_addr(g_w2T);

    cudaFuncSetAttribute(mma_gemm_kernel<128,0,0,0,0,1>, cudaFuncAttributeMaxDynamicSharedMemorySize, DSMEM_TN(128));
    cudaFuncSetAttribute(mma_gemm_kernel<64,1,1,0,1,0>,  cudaFuncAttributeMaxDynamicSharedMemorySize, DSMEM_TN(64));
    cudaFuncSetAttribute(mma_gemm_kernel<128,1,0,1,0,1>, cudaFuncAttributeMaxDynamicSharedMemorySize, DSMEM_TN(128));

    // 1. fused weight packing (one launch)
    pack_all_kernel<<<(PACK_TOTAL + 255) / 256, 256>>>(Wq, Wk, Wv, Wp, W1, W2);

    // 2. LN1 -> fp16
    ln_kernel<<<MM / 8, 256>>>(x, g1, be1, p_h);

    // 3. fused QKV projection -> fp16 qkv  (TN=128: 9x128 grid, ~3.9 waves)
    mma_gemm_kernel<128,0,0,0,0,1><<<dim3(NQKV / 128, MM / 128), 256, DSMEM_TN(128)>>>(
        p_h, p_wqkvT, nullptr, nullptr, nullptr, p_qkvh, MM, NQKV, Cc);

    // 4. flash attention (tensor cores) -> o fp16
    fattn_kernel<<<dim3(Tt / 64, Hh, Bb), 128>>>(p_qkvh, p_o);

    // 5. output projection + bias + residual -> x1 fp32  (TN=64: better waves)
    mma_gemm_kernel<64,1,1,0,1,0><<<dim3(Cc / 64, MM / 128), 256, DSMEM_TN(64)>>>(
        p_o, p_wpT, bp, x, p_x1, nullptr, MM, Cc, Cc);

    // 6. LN2 -> fp16
    ln_kernel<<<MM / 8, 256>>>(p_x1, g2, be2, p_h2);

    // 7. FF1 + bias + relu -> ff fp16  (TN=128)
    mma_gemm_kernel<128,1,0,1,0,1><<<dim3(FF / 128, MM / 128), 256, DSMEM_TN(128)>>>(
        p_h2, p_w1T, b1, nullptr, nullptr, p_ff, MM, FF, Cc);

    // 8. FF2 + bias + residual -> final output fp32  (TN=64)
    mma_gemm_kernel<64,1,1,0,1,0><<<dim3(Cc / 64, MM / 128), 256, DSMEM_TN(64)>>>(
        p_ff, p_w2T, b2, p_x1, out, nullptr, MM, Cc, FF);
}

// round 15
// speedup vs baseline: 1.0163x; 1.0163x over previous
#include <cuda_runtime.h>
#include <cuda_fp16.h>
#include <cstdint>

// Problem dims
#define Bb   64
#define Tt   256
#define Cc   384
#define Hh   6
#define HSZ  64
#define MM   (Bb*Tt)     // 16384 tokens
#define NQKV (3*Cc)      // 1152
#define FF   (4*Cc)      // 1536

// ================= helpers =================
__device__ __forceinline__ uint32_t smem_u32(const void* p) {
    uint32_t a;
    asm("{ .reg .u64 t; cvta.to.shared.u64 t, %1; cvt.u32.u64 %0, t; }" : "=r"(a) : "l"(p));
    return a;
}
#define SMEM_SWIZZLE_128B(off) ((off) ^ (((off) >> 3) & 0x70))

#define CP_ASYNC16(dst, src) \
    asm volatile("cp.async.cg.shared.global [%0], [%1], 16;" :: "r"(dst), "l"(src))
#define CP_COMMIT() asm volatile("cp.async.commit_group;" ::: "memory")
#define CP_WAIT(n)  asm volatile("cp.async.wait_group %0;" :: "n"(n) : "memory")

#define LDSM_X4(r0, r1, r2, r3, addr) \
    asm volatile("ldmatrix.sync.aligned.m8n8.x4.shared.b16 {%0,%1,%2,%3}, [%4];" \
        : "=r"(r0), "=r"(r1), "=r"(r2), "=r"(r3) : "r"(addr))

#define LDSM_X4_T(r0, r1, r2, r3, addr) \
    asm volatile("ldmatrix.sync.aligned.m8n8.x4.trans.shared.b16 {%0,%1,%2,%3}, [%4];" \
        : "=r"(r0), "=r"(r1), "=r"(r2), "=r"(r3) : "r"(addr))

#define MMA16816F16(d, a, b) \
    asm volatile("mma.sync.aligned.m16n8k16.row.col.f32.f16.f16.f32 " \
        "{%0,%1,%2,%3}, {%4,%5,%6,%7}, {%8,%9}, {%0,%1,%2,%3};" \
        : "+f"((d)[0]), "+f"((d)[1]), "+f"((d)[2]), "+f"((d)[3]) \
        : "r"((a)[0]), "r"((a)[1]), "r"((a)[2]), "r"((a)[3]), "r"((b)[0]), "r"((b)[1]))

__device__ __forceinline__ uint32_t pack_h2(float a, float b) {
    __half2 h = __floats2half2_rn(a, b);
    return *reinterpret_cast<uint32_t*>(&h);
}

// ================= scratch (device globals) =================
__device__ __align__(16) __half g_h   [MM*Cc];
__device__ __align__(16) __half g_qkvh[MM*NQKV];   // fp16 q|k|v
__device__ __align__(16) __half g_o   [MM*Cc];
__device__ __align__(16) float  g_x1  [MM*Cc];
__device__ __align__(16) __half g_h2  [MM*Cc];
__device__ __align__(16) __half g_ff  [MM*FF];
// weights: single fp16, transposed to [N][K]
__device__ __align__(16) __half g_wqkvT[NQKV*Cc];
__device__ __align__(16) __half g_wpT  [Cc*Cc];
__device__ __align__(16) __half g_w1T  [FF*Cc];
__device__ __align__(16) __half g_w2T  [Cc*FF];

// ================= fused weight pack (one launch) =================
#define SEG0 (NQKV*Cc)
#define SEG1 (Cc*Cc)
#define SEG2 (FF*Cc)
#define SEG3 (Cc*FF)
#define PACK_TOTAL (SEG0+SEG1+SEG2+SEG3)

__global__ void pack_all_kernel(const float* __restrict__ Wq, const float* __restrict__ Wk,
                                const float* __restrict__ Wv, const float* __restrict__ Wp,
                                const float* __restrict__ W1, const float* __restrict__ W2) {
    int idx = blockIdx.x * 256 + threadIdx.x;
    if (idx < SEG0) {
        int n = idx / Cc, k = idx % Cc;
        int which = n / Cc, hd = n % Cc;
        int h = hd / HSZ, d = hd % HSZ;
        const float* W = (which == 0) ? Wq : (which == 1) ? Wk : Wv;
        g_wqkvT[idx] = __float2half(W[(h * Cc + k) * HSZ + d]);
        return;
    }
    idx -= SEG0;
    if (idx < SEG1) {
        int n = idx / Cc, k = idx % Cc;
        g_wpT[idx] = __float2half(Wp[(size_t)k * Cc + n]);
        return;
    }
    idx -= SEG1;
    if (idx < SEG2) {
        int n = idx / Cc, k = idx % Cc;
        g_w1T[idx] = __float2half(W1[(size_t)k * FF + n]);
        return;
    }
    idx -= SEG2;
    if (idx < SEG3) {
        int n = idx / FF, k = idx % FF;
        g_w2T[idx] = __float2half(W2[(size_t)k * Cc + n]);
        return;
    }
}

// ================= LayerNorm (warp per row) =================
__global__ __launch_bounds__(256)
void ln_kernel(const float* __restrict__ x,
               const float* __restrict__ gamma,
               const float* __restrict__ beta,
               __half* __restrict__ y) {
    int row  = blockIdx.x * 8 + (threadIdx.x >> 5);
    int lane = threadIdx.x & 31;
    const float* xr = x + (size_t)row * Cc;
    float v[12];
    float s = 0.f, sq = 0.f;
    #pragma unroll
    for (int i = 0; i < 12; i++) {
        v[i] = xr[lane + 32 * i];
        s += v[i];
        sq += v[i] * v[i];
    }
    #pragma unroll
    for (int o = 16; o > 0; o >>= 1) {
        s  += __shfl_xor_sync(0xffffffffu, s,  o);
        sq += __shfl_xor_sync(0xffffffffu, sq, o);
    }
    float mu  = s / (float)Cc;
    float inv = rsqrtf(sq / (float)Cc - mu * mu + 1e-3f);
    size_t base = (size_t)row * Cc;
    #pragma unroll
    for (int i = 0; i < 12; i++) {
        int c = lane + 32 * i;
        y[base + c] = __float2half((v[i] - mu) * inv * gamma[c] + beta[c]);
    }
}

// ================= mma.sync fp16 GEMM (TN=128, 3-stage pipeline) ============
#define BUFSZ   32768
#define GEMM_DSMEM (1024 + 3 * BUFSZ)

__device__ __forceinline__ void load_tile_async(const __half* __restrict__ src,
                                                int row0, int k0, int Ktot,
                                                uint32_t dstbase, int tid) {
    #pragma unroll
    for (int j = 0; j < 4; j++) {
        int idx = tid + j * 256;
        int r = idx >> 3, c16 = idx & 7;
        const __half* g = src + (size_t)(row0 + r) * Ktot + k0 + c16 * 8;
        uint32_t s = dstbase + SMEM_SWIZZLE_128B((uint32_t)(r * 128 + c16 * 16));
        CP_ASYNC16(s, g);
    }
}

template<int BIAS, int RES, int RELU, int F32OUT, int HOUT>
__global__ __launch_bounds__(256)
void mma_gemm_kernel(const __half* __restrict__ A,
                     const __half* __restrict__ Bw,
                     const float* __restrict__ bias, const float* __restrict__ res,
                     float* __restrict__ Cf, __half* __restrict__ Ch,
                     int M, int N, int K) {
    extern __shared__ char dsm[];
    uint32_t raw  = smem_u32(dsm);
    uint32_t base = (raw + 1023) & ~1023u;

    int tid = threadIdx.x, wid = tid >> 5, lane = tid & 31;
    int warp_m = (wid >> 2) * 64;
    int warp_n = (wid & 3) * 32;
    int m0 = blockIdx.y * 128, n0 = blockIdx.x * 128;
    int nch = K >> 6;

    float acc[4][4][4];
    #pragma unroll
    for (int a = 0; a < 4; a++)
        #pragma unroll
        for (int b = 0; b < 4; b++)
            #pragma unroll
            for (int c = 0; c < 4; c++) acc[a][b][c] = 0.f;

    // prologue: chunks 0,1 -> bufs 0,1
    load_tile_async(A,  m0, 0, K, base + 0,     tid);
    load_tile_async(Bw, n0, 0, K, base + 16384, tid);
    CP_COMMIT();
    if (nch > 1) {
        load_tile_async(A,  m0, 64, K, base + BUFSZ + 0,     tid);
        load_tile_async(Bw, n0, 64, K, base + BUFSZ + 16384, tid);
        CP_COMMIT();
    }

    int q = lane >> 3, rin = lane & 7;
    int a_row_off = (q & 1) * 8 + rin;
    int a_col_off = (q >> 1) * 8;
    int b_row_off = (q >> 1) * 8 + rin;
    int b_col_off = (q & 1) * 8;

    for (int i = 0; i < nch; i++) {
        if (i + 1 < nch) { CP_WAIT(1); } else { CP_WAIT(0); }
        __syncthreads();

        uint32_t buf = base + (uint32_t)(i % 3) * BUFSZ;
        uint32_t sA = buf + 0, sB = buf + 16384;

        #pragma unroll
        for (int ks = 0; ks < 4; ks++) {
            uint32_t af[4][4], bw[4][2];
            #pragma unroll
            for (int mf = 0; mf < 4; mf++) {
                uint32_t off = (uint32_t)((warp_m + mf * 16 + a_row_off) * 128 +
                                          (ks * 16 + a_col_off) * 2);
                LDSM_X4(af[mf][0], af[mf][1], af[mf][2], af[mf][3],
                        sA + SMEM_SWIZZLE_128B(off));
            }
            #pragma unroll
            for (int nf2 = 0; nf2 < 2; nf2++) {
                uint32_t off = (uint32_t)((warp_n + nf2 * 16 + b_row_off) * 128 +
                                          (ks * 16 + b_col_off) * 2);
                LDSM_X4(bw[nf2 * 2][0], bw[nf2 * 2][1], bw[nf2 * 2 + 1][0], bw[nf2 * 2 + 1][1],
                        sB + SMEM_SWIZZLE_128B(off));
            }
            #pragma unroll
            for (int mf = 0; mf < 4; mf++)
                #pragma unroll
                for (int nf = 0; nf < 4; nf++) MMA16816F16(acc[mf][nf], af[mf], bw[nf]);
        }

        if (i + 2 < nch) {
            uint32_t nb = base + (uint32_t)((i + 2) % 3) * BUFSZ;
            int k0 = (i + 2) << 6;
            load_tile_async(A,  m0, k0, K, nb + 0,     tid);
            load_tile_async(Bw, n0, k0, K, nb + 16384, tid);
            CP_COMMIT();
        }
    }

    int tr = lane >> 2, tc = (lane & 3) * 2;
    #pragma unroll
    for (int mf = 0; mf < 4; mf++) {
        #pragma unroll
        for (int nf = 0; nf < 4; nf++) {
            int col = n0 + warp_n + nf * 8 + tc;
            #pragma unroll
            for (int half = 0; half < 2; half++) {
                int row = m0 + warp_m + mf * 16 + tr + half * 8;
                float v0 = acc[mf][nf][half * 2 + 0];
                float v1 = acc[mf][nf][half * 2 + 1];
                if (BIAS) { v0 += bias[col]; v1 += bias[col + 1]; }
                size_t oidx = (size_t)row * N + col;
                if (RES)  { v0 += res[oidx]; v1 += res[oidx + 1]; }
                if (RELU) { v0 = fmaxf(v0, 0.f); v1 = fmaxf(v1, 0.f); }
                if (F32OUT) { Cf[oidx] = v0; Cf[oidx + 1] = v1; }
                if (HOUT) {
                    Ch[oidx]     = __float2half(v0);
                    Ch[oidx + 1] = __float2half(v1);
                }
            }
        }
    }
}

// ================= flash attention v2: 128 q-rows/block, shared KV ==========
// grid (T/128, H, B), 256 threads (8 warps). Warp w owns q rows [w*16, w*16+16)
// within the block's 128-row Q tile. Warps 0-3 = lower q-tile, 4-7 = upper.
// KV loaded once per block (halves KV gmem traffic vs 64-row blocks).
// smem: Q 16KB | K0 8KB | K1 8KB | V0 8KB | V1 8KB = 48KB.
__device__ __forceinline__ void fattn_load_kv(const __half* __restrict__ qkv,
                                              int b, int h, int kt,
                                              uint32_t kbase, uint32_t vbase, int tid) {
    #pragma unroll
    for (int j = 0; j < 2; j++) {
        int idx = tid + j * 256;
        int r = idx >> 3, c = idx & 7;
        const __half* ks = qkv + (size_t)(b * Tt + kt * 64 + r) * NQKV + Cc + h * HSZ + c * 8;
        CP_ASYNC16(kbase + SMEM_SWIZZLE_128B((uint32_t)(r * 128 + c * 16)), ks);
    }
    #pragma unroll
    for (int j = 0; j < 2; j++) {
        int idx = tid + j * 256;
        int r = idx >> 3, c = idx & 7;
        const __half* vs = qkv + (size_t)(b * Tt + kt * 64 + r) * NQKV + 2 * Cc + h * HSZ + c * 8;
        CP_ASYNC16(vbase + SMEM_SWIZZLE_128B((uint32_t)(r * 128 + c * 16)), vs);
    }
}

__global__ __launch_bounds__(256)
void fattn_kernel(const __half* __restrict__ qkv, __half* __restrict__ o) {
    __shared__ __align__(1024) __half smem[24576];   // 48KB
    int tid = threadIdx.x, wid = tid >> 5, lane = tid & 31;
    int b = blockIdx.z, h = blockIdx.y, bx = blockIdx.x;
    uint32_t sbase = smem_u32(smem);
    uint32_t qb  = sbase;                       // 16KB: 128 rows
    uint32_t kb0 = sbase + 16384, kb1 = kb0 + 8192;
    uint32_t vb0 = kb1 + 8192,    vb1 = vb0 + 8192;

    int qt_own = bx * 2 + (wid >> 2);   // this warp's 64-row q-tile index
    int qt_hi  = bx * 2 + 1;

    // prologue: Q (128 rows) + KV tile 0
    #pragma unroll
    for (int j = 0; j < 4; j++) {
        int idx = tid + j * 256;
        int r = idx >> 3, c = idx & 7;
        const __half* src = qkv + (size_t)(b * Tt + bx * 128 + r) * NQKV + h * HSZ + c * 8;
        CP_ASYNC16(qb + SMEM_SWIZZLE_128B((uint32_t)(r * 128 + c * 16)), src);
    }
    fattn_load_kv(qkv, b, h, 0, kb0, vb0, tid);
    CP_COMMIT();
    CP_WAIT(0);
    __syncthreads();

    int q8 = lane >> 3, rin = lane & 7;
    int a_row = (q8 & 1) * 8 + rin, a_col = (q8 >> 1) * 8;
    int b_row = (q8 >> 1) * 8 + rin, b_col = (q8 & 1) * 8;
    int vm = lane >> 3;
    int v_row = (vm & 1) * 8 + (lane & 7);
    int v_col = (vm >> 1) * 8;
    int tg = lane & 3, gid = lane >> 2;

    uint32_t qf[4][4];
    #pragma unroll
    for (int kc = 0; kc < 4; kc++)
        LDSM_X4(qf[kc][0], qf[kc][1], qf[kc][2], qf[kc][3],
                qb + SMEM_SWIZZLE_128B((uint32_t)((wid * 16 + a_row) * 128 + (kc * 16 + a_col) * 2)));

    float oacc[8][4];
    #pragma unroll
    for (int d = 0; d < 8; d++)
        #pragma unroll
        for (int e = 0; e < 4; e++) oacc[d][e] = 0.f;
    float m0 = -1e30f, m1 = -1e30f, l0 = 0.f, l1 = 0.f;

    for (int kt = 0; kt <= qt_hi; kt++) {
        uint32_t kb = (kt & 1) ? kb1 : kb0;
        uint32_t vb = (kt & 1) ? vb1 : vb0;
        if (kt < qt_hi) {
            fattn_load_kv(qkv, b, h, kt + 1, (kt & 1) ? kb0 : kb1, (kt & 1) ? vb0 : vb1, tid);
            CP_COMMIT();
        }

        if (kt <= qt_own) {
            // ---- S = Q K^T ----
            float sacc[8][4];
            #pragma unroll
            for (int n = 0; n < 8; n++)
                #pragma unroll
                for (int e = 0; e < 4; e++) sacc[n][e] = 0.f;
            #pragma unroll
            for (int kc = 0; kc < 4; kc++) {
                uint32_t bw[8][2];
                #pragma unroll
                for (int nf2 = 0; nf2 < 4; nf2++)
                    LDSM_X4(bw[nf2 * 2][0], bw[nf2 * 2][1], bw[nf2 * 2 + 1][0], bw[nf2 * 2 + 1][1],
                            kb + SMEM_SWIZZLE_128B((uint32_t)((nf2 * 16 + b_row) * 128 + (kc * 16 + b_col) * 2)));
                #pragma unroll
                for (int nf = 0; nf < 8; nf++) MMA16816F16(sacc[nf], qf[kc], bw[nf]);
            }

            #pragma unroll
            for (int nf = 0; nf < 8; nf++)
                #pragma unroll
                for (int e = 0; e < 4; e++) sacc[nf][e] *= 0.125f;
            if (kt == qt_own) {
                // local q row within this 64-row diag tile
                int r0 = (wid & 3) * 16 + gid, r1 = r0 + 8;
                #pragma unroll
                for (int nf = 0; nf < 8; nf++) {
                    int c0 = nf * 8 + tg * 2;
                    if (c0     > r0) sacc[nf][0] = -1e30f;
                    if (c0 + 1 > r0) sacc[nf][1] = -1e30f;
                    if (c0     > r1) sacc[nf][2] = -1e30f;
                    if (c0 + 1 > r1) sacc[nf][3] = -1e30f;
                }
            }

            // ---- online softmax ----
            float rm0 = -1e30f, rm1 = -1e30f;
            #pragma unroll
            for (int nf = 0; nf < 8; nf++) {
                rm0 = fmaxf(rm0, fmaxf(sacc[nf][0], sacc[nf][1]));
                rm1 = fmaxf(rm1, fmaxf(sacc[nf][2], sacc[nf][3]));
            }
            rm0 = fmaxf(rm0, __shfl_xor_sync(0xffffffffu, rm0, 1));
            rm0 = fmaxf(rm0, __shfl_xor_sync(0xffffffffu, rm0, 2));
            rm1 = fmaxf(rm1, __shfl_xor_sync(0xffffffffu, rm1, 1));
            rm1 = fmaxf(rm1, __shfl_xor_sync(0xffffffffu, rm1, 2));
            float mn0 = fmaxf(m0, rm0), mn1 = fmaxf(m1, rm1);
            float cr0 = __expf(m0 - mn0), cr1 = __expf(m1 - mn1);
            l0 *= cr0; l1 *= cr1;
            #pragma unroll
            for (int d = 0; d < 8; d++) {
                oacc[d][0] *= cr0; oacc[d][1] *= cr0;
                oacc[d][2] *= cr1; oacc[d][3] *= cr1;
            }
            m0 = mn0; m1 = mn1;

            uint32_t pf[4][4];
            #pragma unroll
            for (int sf = 0; sf < 4; sf++) {
                float e00 = __expf(sacc[2 * sf][0] - m0);
                float e01 = __expf(sacc[2 * sf][1] - m0);
                float e02 = __expf(sacc[2 * sf][2] - m1);
                float e03 = __expf(sacc[2 * sf][3] - m1);
                float e10 = __expf(sacc[2 * sf + 1][0] - m0);
                float e11 = __expf(sacc[2 * sf + 1][1] - m0);
                float e12 = __expf(sacc[2 * sf + 1][2] - m1);
                float e13 = __expf(sacc[2 * sf + 1][3] - m1);
                l0 += e00 + e01 + e10 + e11;
                l1 += e02 + e03 + e12 + e13;
                pf[sf][0] = pack_h2(e00, e01);
                pf[sf][1] = pack_h2(e02, e03);
                pf[sf][2] = pack_h2(e10, e11);
                pf[sf][3] = pack_h2(e12, e13);
            }

            // ---- O += P V ----
            #pragma unroll
            for (int sf = 0; sf < 4; sf++) {
                uint32_t vf[8][2];
                #pragma unroll
                for (int dp = 0; dp < 4; dp++)
                    LDSM_X4_T(vf[dp * 2][0], vf[dp * 2][1], vf[dp * 2 + 1][0], vf[dp * 2 + 1][1],
                              vb + SMEM_SWIZZLE_128B((uint32_t)((sf * 16 + v_row) * 128 + (dp * 16 + v_col) * 2)));
                #pragma unroll
                for (int df = 0; df < 8; df++) MMA16816F16(oacc[df], pf[sf], vf[df]);
            }
        }

        if (kt < qt_hi) { CP_WAIT(0); __syncthreads(); }
    }

    l0 += __shfl_xor_sync(0xffffffffu, l0, 1);
    l0 += __shfl_xor_sync(0xffffffffu, l0, 2);
    l1 += __shfl_xor_sync(0xffffffffu, l1, 1);
    l1 += __shfl_xor_sync(0xffffffffu, l1, 2);
    float i0 = 1.f / l0, i1 = 1.f / l1;
    size_t tok0 = (size_t)(b * Tt + bx * 128 + wid * 16 + gid);
    #pragma unroll
    for (int df = 0; df < 8; df++) {
        int col = h * HSZ + df * 8 + tg * 2;
        __half2 h0 = __floats2half2_rn(oacc[df][0] * i0, oacc[df][1] * i0);
        *reinterpret_cast<__half2*>(o + tok0 * Cc + col) = h0;
        __half2 h1 = __floats2half2_rn(oacc[df][2] * i1, oacc[df][3] * i1);
        *reinterpret_cast<__half2*>(o + (tok0 + 8) * Cc + col) = h1;
    }
}

// ================= host launch =================
template <typename T>
static T* sym_addr(const T* symbol) {
    void* p = nullptr;
    cudaGetSymbolAddress(&p, (const void*)symbol);
    return (T*)p;
}

extern "C" void kernel_launch(void* const* d_in, const int* in_sizes, int n_in,
                              void* d_out, int out_size) {
    const float* x   = (const float*)d_in[0];
    const float* Wq  = (const float*)d_in[1];
    const float* Wk  = (const float*)d_in[2];
    const float* Wv  = (const float*)d_in[3];
    const float* Wp  = (const float*)d_in[4];
    const float* bp  = (const float*)d_in[5];
    const float* W1  = (const float*)d_in[6];
    const float* b1  = (const float*)d_in[7];
    const float* W2  = (const float*)d_in[8];
    const float* b2  = (const float*)d_in[9];
    const float* g1  = (const float*)d_in[10];
    const float* be1 = (const float*)d_in[11];
    const float* g2  = (const float*)d_in[12];
    const float* be2 = (const float*)d_in[13];
    float* out = (float*)d_out;

    __half* p_h    = sym_addr(g_h);
    __half* p_qkvh = sym_addr(g_qkvh);
    __half* p_o    = sym_addr(g_o);
    float*  p_x1   = sym_addr(g_x1);
    __half* p_h2   = sym_addr(g_h2);
    __half* p_ff   = sym_addr(g_ff);
    __half* p_wqkvT = sym_addr(g_wqkvT);
    __half* p_wpT   = sym_addr(g_wpT);
    __half* p_w1T   = sym_addr(g_w1T);
    __half* p_w2T   = sym_addr(g_w2T);

    cudaFuncSetAttribute(mma_gemm_kernel<0,0,0,0,1>, cudaFuncAttributeMaxDynamicSharedMemorySize, GEMM_DSMEM);
    cudaFuncSetAttribute(mma_gemm_kernel<1,1,0,1,0>, cudaFuncAttributeMaxDynamicSharedMemorySize, GEMM_DSMEM);
    cudaFuncSetAttribute(mma_gemm_kernel<1,0,1,0,1>, cudaFuncAttributeMaxDynamicSharedMemorySize, GEMM_DSMEM);

    // 1. fused weight packing (one launch)
    pack_all_kernel<<<(PACK_TOTAL + 255) / 256, 256>>>(Wq, Wk, Wv, Wp, W1, W2);

    // 2. LN1 -> fp16
    ln_kernel<<<MM / 8, 256>>>(x, g1, be1, p_h);

    // 3. fused QKV projection -> fp16 qkv
    mma_gemm_kernel<0,0,0,0,1><<<dim3(NQKV / 128, MM / 128), 256, GEMM_DSMEM>>>(
        p_h, p_wqkvT, nullptr, nullptr, nullptr, p_qkvh, MM, NQKV, Cc);

    // 4. flash attention v2 (128 q-rows/block) -> o fp16
    fattn_kernel<<<dim3(Tt / 128, Hh, Bb), 256>>>(p_qkvh, p_o);

    // 5. output projection + bias + residual -> x1 fp32
    mma_gemm_kernel<1,1,0,1,0><<<dim3(Cc / 128, MM / 128), 256, GEMM_DSMEM>>>(
        p_o, p_wpT, bp, x, p_x1, nullptr, MM, Cc, Cc);

    // 6. LN2 -> fp16
    ln_kernel<<<MM / 8, 256>>>(p_x1, g2, be2, p_h2);

    // 7. FF1 + bias + relu -> ff fp16
    mma_gemm_kernel<1,0,1,0,1><<<dim3(FF / 128, MM / 128), 256, GEMM_DSMEM>>>(
        p_h2, p_w1T, b1, nullptr, nullptr, p_ff, MM, FF, Cc);

    // 8. FF2 + bias + residual -> final output fp32
    mma_gemm_kernel<1,1,0,1,0><<<dim3(Cc / 128, MM / 128), 256, GEMM_DSMEM>>>(
        p_ff, p_w2T, b2, p_x1, out, nullptr, MM, Cc, FF);
}

// round 16
// speedup vs baseline: 1.0178x; 1.0015x over previous
#include <cuda_runtime.h>
#include <cuda_fp16.h>
#include <cstdint>

// Problem dims
#define Bb   64
#define Tt   256
#define Cc   384
#define Hh   6
#define HSZ  64
#define MM   (Bb*Tt)     // 16384 tokens
#define NQKV (3*Cc)      // 1152
#define FF   (4*Cc)      // 1536

// ================= helpers =================
__device__ __forceinline__ uint32_t smem_u32(const void* p) {
    uint32_t a;
    asm("{ .reg .u64 t; cvta.to.shared.u64 t, %1; cvt.u32.u64 %0, t; }" : "=r"(a) : "l"(p));
    return a;
}
#define SMEM_SWIZZLE_128B(off) ((off) ^ (((off) >> 3) & 0x70))

#define CP_ASYNC16(dst, src) \
    asm volatile("cp.async.cg.shared.global [%0], [%1], 16;" :: "r"(dst), "l"(src))
#define CP_COMMIT() asm volatile("cp.async.commit_group;" ::: "memory")
#define CP_WAIT(n)  asm volatile("cp.async.wait_group %0;" :: "n"(n) : "memory")

#define LDSM_X4(r0, r1, r2, r3, addr) \
    asm volatile("ldmatrix.sync.aligned.m8n8.x4.shared.b16 {%0,%1,%2,%3}, [%4];" \
        : "=r"(r0), "=r"(r1), "=r"(r2), "=r"(r3) : "r"(addr))

#define LDSM_X4_T(r0, r1, r2, r3, addr) \
    asm volatile("ldmatrix.sync.aligned.m8n8.x4.trans.shared.b16 {%0,%1,%2,%3}, [%4];" \
        : "=r"(r0), "=r"(r1), "=r"(r2), "=r"(r3) : "r"(addr))

#define MMA16816F16(d, a, b) \
    asm volatile("mma.sync.aligned.m16n8k16.row.col.f32.f16.f16.f32 " \
        "{%0,%1,%2,%3}, {%4,%5,%6,%7}, {%8,%9}, {%0,%1,%2,%3};" \
        : "+f"((d)[0]), "+f"((d)[1]), "+f"((d)[2]), "+f"((d)[3]) \
        : "r"((a)[0]), "r"((a)[1]), "r"((a)[2]), "r"((a)[3]), "r"((b)[0]), "r"((b)[1]))

__device__ __forceinline__ uint32_t pack_h2(float a, float b) {
    __half2 h = __floats2half2_rn(a, b);
    return *reinterpret_cast<uint32_t*>(&h);
}

// ================= scratch (device globals) =================
__device__ __align__(16) __half g_h   [MM*Cc];
__device__ __align__(16) __half g_qkvh[MM*NQKV];   // fp16 q|k|v
__device__ __align__(16) __half g_o   [MM*Cc];
__device__ __align__(16) float  g_x1  [MM*Cc];
__device__ __align__(16) __half g_h2  [MM*Cc];
__device__ __align__(16) __half g_ff  [MM*FF];
// weights: single fp16, transposed to [N][K]
__device__ __align__(16) __half g_wqkvT[NQKV*Cc];
__device__ __align__(16) __half g_wpT  [Cc*Cc];
__device__ __align__(16) __half g_w1T  [FF*Cc];
__device__ __align__(16) __half g_w2T  [Cc*FF];

// ================= fused weight pack (one launch) =================
#define SEG0 (NQKV*Cc)
#define SEG1 (Cc*Cc)
#define SEG2 (FF*Cc)
#define SEG3 (Cc*FF)
#define PACK_TOTAL (SEG0+SEG1+SEG2+SEG3)

__global__ void pack_all_kernel(const float* __restrict__ Wq, const float* __restrict__ Wk,
                                const float* __restrict__ Wv, const float* __restrict__ Wp,
                                const float* __restrict__ W1, const float* __restrict__ W2) {
    int idx = blockIdx.x * 256 + threadIdx.x;
    if (idx < SEG0) {
        int n = idx / Cc, k = idx % Cc;
        int which = n / Cc, hd = n % Cc;
        int h = hd / HSZ, d = hd % HSZ;
        const float* W = (which == 0) ? Wq : (which == 1) ? Wk : Wv;
        g_wqkvT[idx] = __float2half(W[(h * Cc + k) * HSZ + d]);
        return;
    }
    idx -= SEG0;
    if (idx < SEG1) {
        int n = idx / Cc, k = idx % Cc;
        g_wpT[idx] = __float2half(Wp[(size_t)k * Cc + n]);
        return;
    }
    idx -= SEG1;
    if (idx < SEG2) {
        int n = idx / Cc, k = idx % Cc;
        g_w1T[idx] = __float2half(W1[(size_t)k * FF + n]);
        return;
    }
    idx -= SEG2;
    if (idx < SEG3) {
        int n = idx / FF, k = idx % FF;
        g_w2T[idx] = __float2half(W2[(size_t)k * Cc + n]);
        return;
    }
}

// ================= LayerNorm (warp per row) =================
__global__ __launch_bounds__(256)
void ln_kernel(const float* __restrict__ x,
               const float* __restrict__ gamma,
               const float* __restrict__ beta,
               __half* __restrict__ y) {
    int row  = blockIdx.x * 8 + (threadIdx.x >> 5);
    int lane = threadIdx.x & 31;
    const float* xr = x + (size_t)row * Cc;
    float v[12];
    float s = 0.f, sq = 0.f;
    #pragma unroll
    for (int i = 0; i < 12; i++) {
        v[i] = xr[lane + 32 * i];
        s += v[i];
        sq += v[i] * v[i];
    }
    #pragma unroll
    for (int o = 16; o > 0; o >>= 1) {
        s  += __shfl_xor_sync(0xffffffffu, s,  o);
        sq += __shfl_xor_sync(0xffffffffu, sq, o);
    }
    float mu  = s / (float)Cc;
    float inv = rsqrtf(sq / (float)Cc - mu * mu + 1e-3f);
    size_t base = (size_t)row * Cc;
    #pragma unroll
    for (int i = 0; i < 12; i++) {
        int c = lane + 32 * i;
        y[base + c] = __float2half((v[i] - mu) * inv * gamma[c] + beta[c]);
    }
}

// ================= mma.sync fp16 GEMM, templated tile-M =====================
// C[M,N] = A[M,K] * B^T, A=[M][K] fp16, B=[N][K] fp16.
// CTA tile TM x 128, BK=64, 3-stage cp.async pipeline, one barrier per chunk.
// 256 threads / 8 warps, warp grid 2(m) x 4(n) -> warp tile (TM/2) x 32.
// TM=128 for big-N GEMMs; TM=64 for N=384 GEMMs (wave-quantization smoothing;
// M-split duplicates only B reads, which are small L2-resident weights).
template<int ROWS>
__device__ __forceinline__ void load_tile_async(const __half* __restrict__ src,
                                                int row0, int k0, int Ktot,
                                                uint32_t dstbase, int tid) {
    #pragma unroll
    for (int j = 0; j < ROWS / 32; j++) {
        int idx = tid + j * 256;
        int r = idx >> 3, c16 = idx & 7;
        const __half* g = src + (size_t)(row0 + r) * Ktot + k0 + c16 * 8;
        uint32_t s = dstbase + SMEM_SWIZZLE_128B((uint32_t)(r * 128 + c16 * 16));
        CP_ASYNC16(s, g);
    }
}

template<int TM, int BIAS, int RES, int RELU, int F32OUT, int HOUT>
__global__ __launch_bounds__(256)
void mma_gemm_kernel(const __half* __restrict__ A,
                     const __half* __restrict__ Bw,
                     const float* __restrict__ bias, const float* __restrict__ res,
                     float* __restrict__ Cf, __half* __restrict__ Ch,
                     int M, int N, int K) {
    constexpr int MF = TM / 32;                 // m-fragments per warp (4 or 2)
    constexpr uint32_t ABYTES = TM * 128;       // A tile bytes per stage
    constexpr uint32_t BBYTES = 16384;
    constexpr uint32_t BUF    = ABYTES + BBYTES;

    extern __shared__ char dsm[];
    uint32_t raw  = smem_u32(dsm);
    uint32_t base = (raw + 1023) & ~1023u;

    int tid = threadIdx.x, wid = tid >> 5, lane = tid & 31;
    int warp_m = (wid >> 2) * (TM / 2);
    int warp_n = (wid & 3) * 32;
    int m0 = blockIdx.y * TM, n0 = blockIdx.x * 128;
    int nch = K >> 6;

    float acc[MF][4][4];
    #pragma unroll
    for (int a = 0; a < MF; a++)
        #pragma unroll
        for (int b = 0; b < 4; b++)
            #pragma unroll
            for (int c = 0; c < 4; c++) acc[a][b][c] = 0.f;

    // prologue: chunks 0,1 -> bufs 0,1
    load_tile_async<TM >(A,  m0, 0, K, base + 0,      tid);
    load_tile_async<128>(Bw, n0, 0, K, base + ABYTES, tid);
    CP_COMMIT();
    if (nch > 1) {
        load_tile_async<TM >(A,  m0, 64, K, base + BUF + 0,      tid);
        load_tile_async<128>(Bw, n0, 64, K, base + BUF + ABYTES, tid);
        CP_COMMIT();
    }

    int q = lane >> 3, rin = lane & 7;
    int a_row_off = (q & 1) * 8 + rin;
    int a_col_off = (q >> 1) * 8;
    int b_row_off = (q >> 1) * 8 + rin;
    int b_col_off = (q & 1) * 8;

    for (int i = 0; i < nch; i++) {
        if (i + 1 < nch) { CP_WAIT(1); } else { CP_WAIT(0); }
        __syncthreads();

        uint32_t buf = base + (uint32_t)(i % 3) * BUF;
        uint32_t sA = buf + 0, sB = buf + ABYTES;

        #pragma unroll
        for (int ks = 0; ks < 4; ks++) {
            uint32_t af[MF][4], bw[4][2];
            #pragma unroll
            for (int mf = 0; mf < MF; mf++) {
                uint32_t off = (uint32_t)((warp_m + mf * 16 + a_row_off) * 128 +
                                          (ks * 16 + a_col_off) * 2);
                LDSM_X4(af[mf][0], af[mf][1], af[mf][2], af[mf][3],
                        sA + SMEM_SWIZZLE_128B(off));
            }
            #pragma unroll
            for (int nf2 = 0; nf2 < 2; nf2++) {
                uint32_t off = (uint32_t)((warp_n + nf2 * 16 + b_row_off) * 128 +
                                          (ks * 16 + b_col_off) * 2);
                LDSM_X4(bw[nf2 * 2][0], bw[nf2 * 2][1], bw[nf2 * 2 + 1][0], bw[nf2 * 2 + 1][1],
                        sB + SMEM_SWIZZLE_128B(off));
            }
            #pragma unroll
            for (int mf = 0; mf < MF; mf++)
                #pragma unroll
                for (int nf = 0; nf < 4; nf++) MMA16816F16(acc[mf][nf], af[mf], bw[nf]);
        }

        if (i + 2 < nch) {
            uint32_t nb = base + (uint32_t)((i + 2) % 3) * BUF;
            int k0 = (i + 2) << 6;
            load_tile_async<TM >(A,  m0, k0, K, nb + 0,      tid);
            load_tile_async<128>(Bw, n0, k0, K, nb + ABYTES, tid);
            CP_COMMIT();
        }
    }

    int tr = lane >> 2, tc = (lane & 3) * 2;
    #pragma unroll
    for (int mf = 0; mf < MF; mf++) {
        #pragma unroll
        for (int nf = 0; nf < 4; nf++) {
            int col = n0 + warp_n + nf * 8 + tc;
            #pragma unroll
            for (int half = 0; half < 2; half++) {
                int row = m0 + warp_m + mf * 16 + tr + half * 8;
                float v0 = acc[mf][nf][half * 2 + 0];
                float v1 = acc[mf][nf][half * 2 + 1];
                if (BIAS) { v0 += bias[col]; v1 += bias[col + 1]; }
                size_t oidx = (size_t)row * N + col;
                if (RES)  { v0 += res[oidx]; v1 += res[oidx + 1]; }
                if (RELU) { v0 = fmaxf(v0, 0.f); v1 = fmaxf(v1, 0.f); }
                if (F32OUT) { Cf[oidx] = v0; Cf[oidx + 1] = v1; }
                if (HOUT) {
                    Ch[oidx]     = __float2half(v0);
                    Ch[oidx + 1] = __float2half(v1);
                }
            }
        }
    }
}

// ================= flash attention v2: 128 q-rows/block, shared KV ==========
__device__ __forceinline__ void fattn_load_kv(const __half* __restrict__ qkv,
                                              int b, int h, int kt,
                                              uint32_t kbase, uint32_t vbase, int tid) {
    #pragma unroll
    for (int j = 0; j < 2; j++) {
        int idx = tid + j * 256;
        int r = idx >> 3, c = idx & 7;
        const __half* ks = qkv + (size_t)(b * Tt + kt * 64 + r) * NQKV + Cc + h * HSZ + c * 8;
        CP_ASYNC16(kbase + SMEM_SWIZZLE_128B((uint32_t)(r * 128 + c * 16)), ks);
    }
    #pragma unroll
    for (int j = 0; j < 2; j++) {
        int idx = tid + j * 256;
        int r = idx >> 3, c = idx & 7;
        const __half* vs = qkv + (size_t)(b * Tt + kt * 64 + r) * NQKV + 2 * Cc + h * HSZ + c * 8;
        CP_ASYNC16(vbase + SMEM_SWIZZLE_128B((uint32_t)(r * 128 + c * 16)), vs);
    }
}

__global__ __launch_bounds__(256)
void fattn_kernel(const __half* __restrict__ qkv, __half* __restrict__ o) {
    __shared__ __align__(1024) __half smem[24576];   // 48KB
    int tid = threadIdx.x, wid = tid >> 5, lane = tid & 31;
    int b = blockIdx.z, h = blockIdx.y, bx = blockIdx.x;
    uint32_t sbase = smem_u32(smem);
    uint32_t qb  = sbase;
    uint32_t kb0 = sbase + 16384, kb1 = kb0 + 8192;
    uint32_t vb0 = kb1 + 8192,    vb1 = vb0 + 8192;

    int qt_own = bx * 2 + (wid >> 2);
    int qt_hi  = bx * 2 + 1;

    #pragma unroll
    for (int j = 0; j < 4; j++) {
        int idx = tid + j * 256;
        int r = idx >> 3, c = idx & 7;
        const __half* src = qkv + (size_t)(b * Tt + bx * 128 + r) * NQKV + h * HSZ + c * 8;
        CP_ASYNC16(qb + SMEM_SWIZZLE_128B((uint32_t)(r * 128 + c * 16)), src);
    }
    fattn_load_kv(qkv, b, h, 0, kb0, vb0, tid);
    CP_COMMIT();
    CP_WAIT(0);
    __syncthreads();

    int q8 = lane >> 3, rin = lane & 7;
    int a_row = (q8 & 1) * 8 + rin, a_col = (q8 >> 1) * 8;
    int b_row = (q8 >> 1) * 8 + rin, b_col = (q8 & 1) * 8;
    int vm = lane >> 3;
    int v_row = (vm & 1) * 8 + (lane & 7);
    int v_col = (vm >> 1) * 8;
    int tg = lane & 3, gid = lane >> 2;

    uint32_t qf[4][4];
    #pragma unroll
    for (int kc = 0; kc < 4; kc++)
        LDSM_X4(qf[kc][0], qf[kc][1], qf[kc][2], qf[kc][3],
                qb + SMEM_SWIZZLE_128B((uint32_t)((wid * 16 + a_row) * 128 + (kc * 16 + a_col) * 2)));

    float oacc[8][4];
    #pragma unroll
    for (int d = 0; d < 8; d++)
        #pragma unroll
        for (int e = 0; e < 4; e++) oacc[d][e] = 0.f;
    float m0 = -1e30f, m1 = -1e30f, l0 = 0.f, l1 = 0.f;

    for (int kt = 0; kt <= qt_hi; kt++) {
        uint32_t kb = (kt & 1) ? kb1 : kb0;
        uint32_t vb = (kt & 1) ? vb1 : vb0;
        if (kt < qt_hi) {
            fattn_load_kv(qkv, b, h, kt + 1, (kt & 1) ? kb0 : kb1, (kt & 1) ? vb0 : vb1, tid);
            CP_COMMIT();
        }

        if (kt <= qt_own) {
            float sacc[8][4];
            #pragma unroll
            for (int n = 0; n < 8; n++)
                #pragma unroll
                for (int e = 0; e < 4; e++) sacc[n][e] = 0.f;
            #pragma unroll
            for (int kc = 0; kc < 4; kc++) {
                uint32_t bw[8][2];
                #pragma unroll
                for (int nf2 = 0; nf2 < 4; nf2++)
                    LDSM_X4(bw[nf2 * 2][0], bw[nf2 * 2][1], bw[nf2 * 2 + 1][0], bw[nf2 * 2 + 1][1],
                            kb + SMEM_SWIZZLE_128B((uint32_t)((nf2 * 16 + b_row) * 128 + (kc * 16 + b_col) * 2)));
                #pragma unroll
                for (int nf = 0; nf < 8; nf++) MMA16816F16(sacc[nf], qf[kc], bw[nf]);
            }

            #pragma unroll
            for (int nf = 0; nf < 8; nf++)
                #pragma unroll
                for (int e = 0; e < 4; e++) sacc[nf][e] *= 0.125f;
            if (kt == qt_own) {
                int r0 = (wid & 3) * 16 + gid, r1 = r0 + 8;
                #pragma unroll
                for (int nf = 0; nf < 8; nf++) {
                    int c0 = nf * 8 + tg * 2;
                    if (c0     > r0) sacc[nf][0] = -1e30f;
                    if (c0 + 1 > r0) sacc[nf][1] = -1e30f;
                    if (c0     > r1) sacc[nf][2] = -1e30f;
                    if (c0 + 1 > r1) sacc[nf][3] = -1e30f;
                }
            }

            float rm0 = -1e30f, rm1 = -1e30f;
            #pragma unroll
            for (int nf = 0; nf < 8; nf++) {
                rm0 = fmaxf(rm0, fmaxf(sacc[nf][0], sacc[nf][1]));
                rm1 = fmaxf(rm1, fmaxf(sacc[nf][2], sacc[nf][3]));
            }
            rm0 = fmaxf(rm0, __shfl_xor_sync(0xffffffffu, rm0, 1));
            rm0 = fmaxf(rm0, __shfl_xor_sync(0xffffffffu, rm0, 2));
            rm1 = fmaxf(rm1, __shfl_xor_sync(0xffffffffu, rm1, 1));
            rm1 = fmaxf(rm1, __shfl_xor_sync(0xffffffffu, rm1, 2));
            float mn0 = fmaxf(m0, rm0), mn1 = fmaxf(m1, rm1);
            float cr0 = __expf(m0 - mn0), cr1 = __expf(m1 - mn1);
            l0 *= cr0; l1 *= cr1;
            #pragma unroll
            for (int d = 0; d < 8; d++) {
                oacc[d][0] *= cr0; oacc[d][1] *= cr0;
                oacc[d][2] *= cr1; oacc[d][3] *= cr1;
            }
            m0 = mn0; m1 = mn1;

            uint32_t pf[4][4];
            #pragma unroll
            for (int sf = 0; sf < 4; sf++) {
                float e00 = __expf(sacc[2 * sf][0] - m0);
                float e01 = __expf(sacc[2 * sf][1] - m0);
                float e02 = __expf(sacc[2 * sf][2] - m1);
                float e03 = __expf(sacc[2 * sf][3] - m1);
                float e10 = __expf(sacc[2 * sf + 1][0] - m0);
                float e11 = __expf(sacc[2 * sf + 1][1] - m0);
                float e12 = __expf(sacc[2 * sf + 1][2] - m1);
                float e13 = __expf(sacc[2 * sf + 1][3] - m1);
                l0 += e00 + e01 + e10 + e11;
                l1 += e02 + e03 + e12 + e13;
                pf[sf][0] = pack_h2(e00, e01);
                pf[sf][1] = pack_h2(e02, e03);
                pf[sf][2] = pack_h2(e10, e11);
                pf[sf][3] = pack_h2(e12, e13);
            }

            #pragma unroll
            for (int sf = 0; sf < 4; sf++) {
                uint32_t vf[8][2];
                #pragma unroll
                for (int dp = 0; dp < 4; dp++)
                    LDSM_X4_T(vf[dp * 2][0], vf[dp * 2][1], vf[dp * 2 + 1][0], vf[dp * 2 + 1][1],
                              vb + SMEM_SWIZZLE_128B((uint32_t)((sf * 16 + v_row) * 128 + (dp * 16 + v_col) * 2)));
                #pragma unroll
                for (int df = 0; df < 8; df++) MMA16816F16(oacc[df], pf[sf], vf[df]);
            }
        }

        if (kt < qt_hi) { CP_WAIT(0); __syncthreads(); }
    }

    l0 += __shfl_xor_sync(0xffffffffu, l0, 1);
    l0 += __shfl_xor_sync(0xffffffffu, l0, 2);
    l1 += __shfl_xor_sync(0xffffffffu, l1, 1);
    l1 += __shfl_xor_sync(0xffffffffu, l1, 2);
    float i0 = 1.f / l0, i1 = 1.f / l1;
    size_t tok0 = (size_t)(b * Tt + bx * 128 + wid * 16 + gid);
    #pragma unroll
    for (int df = 0; df < 8; df++) {
        int col = h * HSZ + df * 8 + tg * 2;
        __half2 h0 = __floats2half2_rn(oacc[df][0] * i0, oacc[df][1] * i0);
        *reinterpret_cast<__half2*>(o + tok0 * Cc + col) = h0;
        __half2 h1 = __floats2half2_rn(oacc[df][2] * i1, oacc[df][3] * i1);
        *reinterpret_cast<__half2*>(o + (tok0 + 8) * Cc + col) = h1;
    }
}

// ================= host launch =================
template <typename T>
static T* sym_addr(const T* symbol) {
    void* p = nullptr;
    cudaGetSymbolAddress(&p, (const void*)symbol);
    return (T*)p;
}

#define DSMEM_TM(TM) (1024 + 3 * ((TM) * 128 + 16384))

extern "C" void kernel_launch(void* const* d_in, const int* in_sizes, int n_in,
                              void* d_out, int out_size) {
    const float* x   = (const float*)d_in[0];
    const float* Wq  = (const float*)d_in[1];
    const float* Wk  = (const float*)d_in[2];
    const float* Wv  = (const float*)d_in[3];
    const float* Wp  = (const float*)d_in[4];
    const float* bp  = (const float*)d_in[5];
    const float* W1  = (const float*)d_in[6];
    const float* b1  = (const float*)d_in[7];
    const float* W2  = (const float*)d_in[8];
    const float* b2  = (const float*)d_in[9];
    const float* g1  = (const float*)d_in[10];
    const float* be1 = (const float*)d_in[11];
    const float* g2  = (const float*)d_in[12];
    const float* be2 = (const float*)d_in[13];
    float* out = (float*)d_out;

    __half* p_h    = sym_addr(g_h);
    __half* p_qkvh = sym_addr(g_qkvh);
    __half* p_o    = sym_addr(g_o);
    float*  p_x1   = sym_addr(g_x1);
    __half* p_h2   = sym_addr(g_h2);
    __half* p_ff   = sym_addr(g_ff);
    __half* p_wqkvT = sym_addr(g_wqkvT);
    __half* p_wpT   = sym_addr(g_wpT);
    __half* p_w1T   = sym_addr(g_w1T);
    __half* p_w2T   = sym_addr(g_w2T);

    cudaFuncSetAttribute(mma_gemm_kernel<128,0,0,0,0,1>, cudaFuncAttributeMaxDynamicSharedMemorySize, DSMEM_TM(128));
    cudaFuncSetAttribute(mma_gemm_kernel<64,1,1,0,1,0>,  cudaFuncAttributeMaxDynamicSharedMemorySize, DSMEM_TM(64));
    cudaFuncSetAttribute(mma_gemm_kernel<128,1,0,1,0,1>, cudaFuncAttributeMaxDynamicSharedMemorySize, DSMEM_TM(128));

    // 1. fused weight packing (one launch)
    pack_all_kernel<<<(PACK_TOTAL + 255) / 256, 256>>>(Wq, Wk, Wv, Wp, W1, W2);

    // 2. LN1 -> fp16
    ln_kernel<<<MM / 8, 256>>>(x, g1, be1, p_h);

    // 3. fused QKV projection -> fp16 qkv  (TM=128)
    mma_gemm_kernel<128,0,0,0,0,1><<<dim3(NQKV / 128, MM / 128), 256, DSMEM_TM(128)>>>(
        p_h, p_wqkvT, nullptr, nullptr, nullptr, p_qkvh, MM, NQKV, Cc);

    // 4. flash attention (128 q-rows/block) -> o fp16
    fattn_kernel<<<dim3(Tt / 128, Hh, Bb), 256>>>(p_qkvh, p_o);

    // 5. output projection + bias + residual -> x1 fp32  (TM=64: wave smoothing)
    mma_gemm_kernel<64,1,1,0,1,0><<<dim3(Cc / 128, MM / 64), 256, DSMEM_TM(64)>>>(
        p_o, p_wpT, bp, x, p_x1, nullptr, MM, Cc, Cc);

    // 6. LN2 -> fp16
    ln_kernel<<<MM / 8, 256>>>(p_x1, g2, be2, p_h2);

    // 7. FF1 + bias + relu -> ff fp16  (TM=128)
    mma_gemm_kernel<128,1,0,1,0,1><<<dim3(FF / 128, MM / 128), 256, DSMEM_TM(128)>>>(
        p_h2, p_w1T, b1, nullptr, nullptr, p_ff, MM, FF, Cc);

    // 8. FF2 + bias + residual -> final output fp32  (TM=64)
    mma_gemm_kernel<64,1,1,0,1,0><<<dim3(Cc / 128, MM / 64), 256, DSMEM_TM(64)>>>(
        p_ff, p_w2T, b2, p_x1, out, nullptr, MM, Cc, FF);
}